// round 2
// baseline (speedup 1.0000x reference)
#include <cuda_runtime.h>

#define HID 64
#define BSZ 1024
#define TSTEPS 64
#define ROWS_PER_CTA 8
#define CTA_THREADS 128
#define GRID_CTAS 128
#define SMEM_BYTES 118016

// Scratch written by precompute kernel, read by main kernel (same stream → ordered).
__device__ float g_Wcomb[HID * HID];     // folded WmixO @ Wof
__device__ float g_tconst[TSTEPS * HID]; // per-step t-branch constant (incl. biases)

__device__ __forceinline__ float sigf(float x) { return 1.0f / (1.0f + __expf(-x)); }
__device__ __forceinline__ float tanha(float x) { return 2.0f / (1.0f + __expf(-2.0f * x)) - 1.0f; }
__device__ __forceinline__ float lrelu(float v) { return v >= 0.0f ? v : 0.1f * v; }
__device__ __forceinline__ float4 f4fma(float4 w, float h, float4 a) {
    a.x = fmaf(w.x, h, a.x); a.y = fmaf(w.y, h, a.y);
    a.z = fmaf(w.z, h, a.z); a.w = fmaf(w.w, h, a.w);
    return a;
}

// ---------------------------------------------------------------------------
// Precompute: t-LSTM sequence (batch-independent, zero input) + weight folding.
// One block, 256 threads. Sequential in s but tiny.
// ---------------------------------------------------------------------------
__global__ void __launch_bounds__(256) precompute_kernel(
    const float* __restrict__ Whh_t, const float* __restrict__ bih_t,
    const float* __restrict__ bhh_t, const float* __restrict__ Wtf,
    const float* __restrict__ btf, const float* __restrict__ Wmix,
    const float* __restrict__ bmix, const float* __restrict__ Wof,
    const float* __restrict__ bof)
{
    __shared__ float h[64], c[64], tsv[64], gsh[256], bofmix[64], part[256];
    const int tid = threadIdx.x;

    // Wcomb[i][l] = sum_k WmixO[i][k] * Wof[k][l]
    for (int idx = tid; idx < 4096; idx += 256) {
        int i = idx >> 6, l = idx & 63;
        float s = 0.f;
#pragma unroll 8
        for (int k = 0; k < 64; k++) s += Wmix[i * 128 + 64 + k] * Wof[k * 64 + l];
        g_Wcomb[idx] = s;
    }
    if (tid < 64) {
        float s = 0.f;
        for (int k = 0; k < 64; k++) s += Wmix[tid * 128 + 64 + k] * bof[k];
        bofmix[tid] = s;
        h[tid] = 0.f;
        c[tid] = 0.f;
    }
    __syncthreads();

    const int j = tid & 63, gate = tid >> 6;
    const float bg = bih_t[gate * 64 + j] + bhh_t[gate * 64 + j];
    const float* wr = Whh_t + (gate * 64 + j) * 64;

    for (int s = 0; s < TSTEPS; s++) {
        float acc = bg; // x == 0 always, so no Wih_t term
#pragma unroll 8
        for (int k = 0; k < 64; k++) acc += wr[k] * h[k];
        gsh[gate * 64 + j] = acc;
        __syncthreads();
        if (gate == 0) {
            float i_ = sigf(gsh[j]), f_ = sigf(gsh[64 + j]);
            float g_ = tanha(gsh[128 + j]), o_ = sigf(gsh[192 + j]);
            float cn = f_ * c[j] + i_ * g_;
            c[j] = cn;
            h[j] = o_ * tanha(cn);
        }
        __syncthreads();
        {
            float p = 0.f;
            const float* w2 = Wtf + j * 64 + gate * 16;
            const float* hh = h + gate * 16;
#pragma unroll
            for (int k = 0; k < 16; k++) p += w2[k] * hh[k];
            part[tid] = p;
        }
        __syncthreads();
        if (gate == 0) tsv[j] = btf[j] + part[j] + part[64 + j] + part[128 + j] + part[192 + j];
        __syncthreads();
        {
            float p = 0.f;
            const float* w3 = Wmix + j * 128 + gate * 16;
            const float* tt = tsv + gate * 16;
#pragma unroll
            for (int k = 0; k < 16; k++) p += w3[k] * tt[k];
            part[tid] = p;
        }
        __syncthreads();
        if (gate == 0)
            g_tconst[s * 64 + j] =
                bmix[j] + bofmix[j] + part[j] + part[64 + j] + part[128 + j] + part[192 + j];
        __syncthreads();
    }
}

// ---------------------------------------------------------------------------
// Main kernel: 128 CTAs x 128 threads. 8 rows/CTA, 16 threads/row,
// 2 rows per warp (half-warps broadcast-share all weight reads).
// All weights in shared; hot loop uses only __syncwarp.
// ---------------------------------------------------------------------------
__global__ void __launch_bounds__(CTA_THREADS) navnet_kernel(
    const float* __restrict__ obsv,
    const float* __restrict__ Wih_o, const float* __restrict__ Whh_o,
    const float* __restrict__ bih_o, const float* __restrict__ bhh_o,
    const float* __restrict__ W1, const float* __restrict__ b1,
    const float* __restrict__ W2, const float* __restrict__ b2,
    const float* __restrict__ W3, const float* __restrict__ b3,
    float* __restrict__ out, int out_size)
{
    extern __shared__ char smem[];
    float4* whh4 = (float4*)(smem);           // [k][j] gates packed (i,f,g,o): 64KB
    float4* wc4  = (float4*)(smem + 65536);   // [k][sub] Wcomb cols (j=sub+16q): 16KB
    float4* tc4  = (float4*)(smem + 81920);   // [s][sub] tconst packed: 16KB
    float4* wih4 = (float4*)(smem + 98304);   // [xi][j] gates packed: 2KB
    float4* bg4  = (float4*)(smem + 100352);  // [j] combined gate bias: 1KB
    float2* w1p  = (float2*)(smem + 101376);  // [k][sub] = {W1[sub][k], W1[sub+16][k]}: 8KB
    float2* w2p  = (float2*)(smem + 109568);  // [k][sub]: 4KB
    float2* b1p  = (float2*)(smem + 113664);
    float2* b2p  = (float2*)(smem + 113792);
    float*  hsh  = (float*)(smem + 113920);   // [8][64]
    float*  msh  = (float*)(smem + 115968);   // [8][64]

    const int tid = threadIdx.x;

    // ---- stage weights into shared (once) ----
    for (int idx = tid; idx < 4096; idx += CTA_THREADS) {
        int k = idx >> 6, j = idx & 63;
        whh4[idx] = make_float4(Whh_o[j * 64 + k], Whh_o[(64 + j) * 64 + k],
                                Whh_o[(128 + j) * 64 + k], Whh_o[(192 + j) * 64 + k]);
    }
    for (int idx = tid; idx < 1024; idx += CTA_THREADS) {
        int k = idx >> 4, sb = idx & 15;
        wc4[idx] = make_float4(g_Wcomb[sb * 64 + k], g_Wcomb[(sb + 16) * 64 + k],
                               g_Wcomb[(sb + 32) * 64 + k], g_Wcomb[(sb + 48) * 64 + k]);
        tc4[idx] = make_float4(g_tconst[k * 64 + sb], g_tconst[k * 64 + sb + 16],
                               g_tconst[k * 64 + sb + 32], g_tconst[k * 64 + sb + 48]);
        w1p[idx] = make_float2(W1[sb * 64 + k], W1[(sb + 16) * 64 + k]);
    }
    for (int idx = tid; idx < 512; idx += CTA_THREADS) {
        int k = idx >> 4, sb = idx & 15;
        w2p[idx] = make_float2(W2[sb * 32 + k], W2[(sb + 16) * 32 + k]);
    }
    if (tid < 128) {
        int xi = tid >> 6, j = tid & 63;
        wih4[tid] = make_float4(Wih_o[j * 2 + xi], Wih_o[(64 + j) * 2 + xi],
                                Wih_o[(128 + j) * 2 + xi], Wih_o[(192 + j) * 2 + xi]);
    }
    if (tid < 64) {
        bg4[tid] = make_float4(bih_o[tid] + bhh_o[tid], bih_o[64 + tid] + bhh_o[64 + tid],
                               bih_o[128 + tid] + bhh_o[128 + tid], bih_o[192 + tid] + bhh_o[192 + tid]);
    }
    if (tid < 16) {
        b1p[tid] = make_float2(b1[tid], b1[tid + 16]);
        b2p[tid] = make_float2(b2[tid], b2[tid + 16]);
    }

    // ---- per-thread mapping ----
    const int lane = tid & 31;
    const int sub  = lane & 15;
    const int rl   = (tid >> 5) * 2 + (lane >> 4);
    const int row  = blockIdx.x * ROWS_PER_CTA + rl;
    float* hrow = hsh + rl * 64;
    float* mrow = msh + rl * 64;
    const float4* hrow4 = (const float4*)hrow;
    const float4* mrow4 = (const float4*)mrow;

    hrow[sub] = 0.f; hrow[sub + 16] = 0.f; hrow[sub + 32] = 0.f; hrow[sub + 48] = 0.f;
    float c0 = 0.f, c1 = 0.f, c2 = 0.f, c3 = 0.f;

    // zero c_out region (second output)
    {
        int cb = BSZ * TSTEPS * 2 + row * TSTEPS;
#pragma unroll
        for (int q = 0; q < 4; q++) {
            int o = cb + sub + 16 * q;
            if (o < out_size) out[o] = 0.f;
        }
    }

    const float w30a = W3[sub], w30b = W3[sub + 16];
    const float w31a = W3[32 + sub], w31b = W3[32 + sub + 16];
    const float b30 = b3[0], b31 = b3[1];

    __syncthreads();

    float b0x, b0y, bu1x, bu1y, bu2x, bu2y;

    auto cell = [&](float x0, float x1) {
        float4 A0 = bg4[sub], A1 = bg4[sub + 16], A2 = bg4[sub + 32], A3 = bg4[sub + 48];
        A0 = f4fma(wih4[sub], x0, A0);       A0 = f4fma(wih4[64 + sub], x1, A0);
        A1 = f4fma(wih4[sub + 16], x0, A1);  A1 = f4fma(wih4[64 + sub + 16], x1, A1);
        A2 = f4fma(wih4[sub + 32], x0, A2);  A2 = f4fma(wih4[64 + sub + 32], x1, A2);
        A3 = f4fma(wih4[sub + 48], x0, A3);  A3 = f4fma(wih4[64 + sub + 48], x1, A3);
#pragma unroll 4
        for (int k4 = 0; k4 < 16; k4++) {
            float4 hv = hrow4[k4];
            int b = k4 * 256;
#define STEPK(hk, off)                                   \
            A0 = f4fma(whh4[b + (off) + sub], hk, A0);       \
            A1 = f4fma(whh4[b + (off) + sub + 16], hk, A1);  \
            A2 = f4fma(whh4[b + (off) + sub + 32], hk, A2);  \
            A3 = f4fma(whh4[b + (off) + sub + 48], hk, A3);
            STEPK(hv.x, 0) STEPK(hv.y, 64) STEPK(hv.z, 128) STEPK(hv.w, 192)
#undef STEPK
        }
        float i_, f_, g_, o_;
        i_ = sigf(A0.x); f_ = sigf(A0.y); g_ = tanha(A0.z); o_ = sigf(A0.w);
        c0 = f_ * c0 + i_ * g_; float h0 = o_ * tanha(c0);
        i_ = sigf(A1.x); f_ = sigf(A1.y); g_ = tanha(A1.z); o_ = sigf(A1.w);
        c1 = f_ * c1 + i_ * g_; float h1 = o_ * tanha(c1);
        i_ = sigf(A2.x); f_ = sigf(A2.y); g_ = tanha(A2.z); o_ = sigf(A2.w);
        c2 = f_ * c2 + i_ * g_; float h2 = o_ * tanha(c2);
        i_ = sigf(A3.x); f_ = sigf(A3.y); g_ = tanha(A3.z); o_ = sigf(A3.w);
        c3 = f_ * c3 + i_ * g_; float h3 = o_ * tanha(c3);
        __syncwarp();
        hrow[sub] = h0; hrow[sub + 16] = h1; hrow[sub + 32] = h2; hrow[sub + 48] = h3;
        __syncwarp();
    };

    auto mix = [&](int s) {
        float4 M = tc4[s * 16 + sub];
#pragma unroll 4
        for (int k4 = 0; k4 < 16; k4++) {
            float4 hv = hrow4[k4];
            int b = k4 * 64;
            M = f4fma(wc4[b + sub], hv.x, M);
            M = f4fma(wc4[b + 16 + sub], hv.y, M);
            M = f4fma(wc4[b + 32 + sub], hv.z, M);
            M = f4fma(wc4[b + 48 + sub], hv.w, M);
        }
        __syncwarp();
        mrow[sub] = M.x; mrow[sub + 16] = M.y; mrow[sub + 32] = M.z; mrow[sub + 48] = M.w;
        __syncwarp();
        float2 bb = b1p[sub];
        float s1 = bb.x, s2 = bb.y;
#pragma unroll 4
        for (int k4 = 0; k4 < 16; k4++) {
            float4 mv = mrow4[k4];
            int b = k4 * 64;
            float2 w;
            w = w1p[b + sub];      s1 = fmaf(w.x, mv.x, s1); s2 = fmaf(w.y, mv.x, s2);
            w = w1p[b + 16 + sub]; s1 = fmaf(w.x, mv.y, s1); s2 = fmaf(w.y, mv.y, s2);
            w = w1p[b + 32 + sub]; s1 = fmaf(w.x, mv.z, s1); s2 = fmaf(w.y, mv.z, s2);
            w = w1p[b + 48 + sub]; s1 = fmaf(w.x, mv.w, s1); s2 = fmaf(w.y, mv.w, s2);
        }
        s1 = lrelu(s1); s2 = lrelu(s2);
        float2 cb2 = b2p[sub];
        float t1 = cb2.x, t2 = cb2.y;
        const int base16 = lane & 16;
#pragma unroll
        for (int k = 0; k < 16; k++) {
            float ak = __shfl_sync(0xffffffffu, s1, base16 + k, 32);
            float2 w = w2p[k * 16 + sub];
            t1 = fmaf(w.x, ak, t1); t2 = fmaf(w.y, ak, t2);
        }
#pragma unroll
        for (int k = 0; k < 16; k++) {
            float ak = __shfl_sync(0xffffffffu, s2, base16 + k, 32);
            float2 w = w2p[(k + 16) * 16 + sub];
            t1 = fmaf(w.x, ak, t1); t2 = fmaf(w.y, ak, t2);
        }
        t1 = lrelu(t1); t2 = lrelu(t2);
        float p0 = t1 * w30a + t2 * w30b;
        float p1 = t1 * w31a + t2 * w31b;
#pragma unroll
        for (int off = 8; off > 0; off >>= 1) {
            p0 += __shfl_xor_sync(0xffffffffu, p0, off, 32);
            p1 += __shfl_xor_sync(0xffffffffu, p1, off, 32);
        }
        float yx = p0 + b30 + bu2x + (bu2x - b0x) * 0.5f;
        float yy = p1 + b31 + bu2y + (bu2y - b0y) * 0.5f;
        if (sub == 0) {
            out[row * (TSTEPS * 2) + s * 2]     = yx;
            out[row * (TSTEPS * 2) + s * 2 + 1] = yy;
        }
        b0x = bu1x; b0y = bu1y; bu1x = bu2x; bu1y = bu2y; bu2x = yx; bu2y = yy;
    };

    // ---- observation scan (8 steps) ----
    const float* orow = obsv + row * 16;
#pragma unroll 1
    for (int t = 0; t < 8; t++) cell(orow[t * 2], orow[t * 2 + 1]);

    b0x = orow[10]; b0y = orow[11];
    bu1x = orow[12]; bu1y = orow[13];
    bu2x = orow[14]; bu2y = orow[15];

    // ---- autoregressive rollout ----
    mix(0);
#pragma unroll 1
    for (int s = 1; s < TSTEPS; s++) {
        cell(bu2x, bu2y);
        mix(s);
    }
}

extern "C" void kernel_launch(void* const* d_in, const int* in_sizes, int n_in,
                              void* d_out, int out_size)
{
    const float* obsv  = (const float*)d_in[0];
    // d_in[1] = teom: intentionally unused (reference feeds zeros into the t-LSTM)
    const float* Wih_o = (const float*)d_in[2];
    const float* Whh_o = (const float*)d_in[3];
    const float* bih_o = (const float*)d_in[4];
    const float* bhh_o = (const float*)d_in[5];
    // d_in[6] = Wih_t: unused (x == 0)
    const float* Whh_t = (const float*)d_in[7];
    const float* bih_t = (const float*)d_in[8];
    const float* bhh_t = (const float*)d_in[9];
    const float* Wof   = (const float*)d_in[10];
    const float* bof   = (const float*)d_in[11];
    const float* Wtf   = (const float*)d_in[12];
    const float* btf   = (const float*)d_in[13];
    const float* Wmix  = (const float*)d_in[14];
    const float* bmix  = (const float*)d_in[15];
    const float* W1    = (const float*)d_in[16];
    const float* b1    = (const float*)d_in[17];
    const float* W2    = (const float*)d_in[18];
    const float* b2    = (const float*)d_in[19];
    const float* W3    = (const float*)d_in[20];
    const float* b3    = (const float*)d_in[21];

    precompute_kernel<<<1, 256>>>(Whh_t, bih_t, bhh_t, Wtf, btf, Wmix, bmix, Wof, bof);

    cudaFuncSetAttribute(navnet_kernel, cudaFuncAttributeMaxDynamicSharedMemorySize, SMEM_BYTES);
    navnet_kernel<<<GRID_CTAS, CTA_THREADS, SMEM_BYTES>>>(
        obsv, Wih_o, Whh_o, bih_o, bhh_o, W1, b1, W2, b2, W3, b3,
        (float*)d_out, out_size);
}

// round 3
// speedup vs baseline: 1.9618x; 1.9618x over previous
#include <cuda_runtime.h>

#define HID 64
#define BSZ 1024
#define TSTEPS 64
#define ROWS_PER_CTA 8
#define CTA_THREADS 128
#define GRID_CTAS 128

// ---- shared memory layout (bytes) ----
// 0       whh4    float4[4096]  65536   (phase1: WhhtT float[64][256])
// 65536   wc4     float4[1024]  16384
// 81920   tc4     float4[1024]  16384
// 98304   wih4    float4[128]   2048
// 100352  bg4     float4[64]    1024
// 101376  w1p     float2[1024]  8192
// 109568  w2p     float2[512]   4096
// 113664  b1p     float2[16]    128
// 113792  b2p     float2[16]    128
// 113920  hsh2    u64[8*64]     4096    (h duplicated-packed per row)
// 118016  msh2    u64[8*64]     4096
// 122112  WtfT    float[4096]   16384   (scratch, transposed [k][j])
// 138496  WmixTT  float[4096]   16384
// 154880  WmixOT  float[4096]   16384
// 171264  tscr    floats        3584
#define SMEM_BYTES 174848

#define OFF_WC    65536
#define OFF_TC    81920
#define OFF_WIH   98304
#define OFF_BG    100352
#define OFF_W1    101376
#define OFF_W2    109568
#define OFF_B1    113664
#define OFF_B2    113792
#define OFF_H2    113920
#define OFF_M2    118016
#define OFF_WTF   122112
#define OFF_WMT   138496
#define OFF_WMO   154880
#define OFF_TSCR  171264

__device__ __forceinline__ float sigf(float x) { return 1.0f / (1.0f + __expf(-x)); }
__device__ __forceinline__ float tanha(float x) { return 2.0f / (1.0f + __expf(-2.0f * x)) - 1.0f; }
__device__ __forceinline__ float lrelu(float v) { return v >= 0.0f ? v : 0.1f * v; }

// packed f32x2 helpers (Blackwell)
__device__ __forceinline__ unsigned long long pk2(float v) {
    unsigned long long r;
    asm("mov.b64 %0, {%1, %1};" : "=l"(r) : "f"(v));
    return r;
}
__device__ __forceinline__ float2 upk(unsigned long long v) {
    float2 f;
    asm("mov.b64 {%0, %1}, %2;" : "=f"(f.x), "=f"(f.y) : "l"(v));
    return f;
}
__device__ __forceinline__ void fma2(unsigned long long& a, unsigned long long w, unsigned long long b) {
    asm("fma.rn.f32x2 %0, %1, %2, %0;" : "+l"(a) : "l"(w), "l"(b));
}

__global__ void __launch_bounds__(CTA_THREADS) navnet_fused_kernel(
    const float* __restrict__ obsv,
    const float* __restrict__ Wih_o, const float* __restrict__ Whh_o,
    const float* __restrict__ bih_o, const float* __restrict__ bhh_o,
    const float* __restrict__ Whh_t, const float* __restrict__ bih_t,
    const float* __restrict__ bhh_t, const float* __restrict__ Wof,
    const float* __restrict__ bof, const float* __restrict__ Wtf,
    const float* __restrict__ btf, const float* __restrict__ Wmix,
    const float* __restrict__ bmix,
    const float* __restrict__ W1, const float* __restrict__ b1,
    const float* __restrict__ W2, const float* __restrict__ b2,
    const float* __restrict__ W3, const float* __restrict__ b3,
    float* __restrict__ out, int out_size)
{
    extern __shared__ char smem[];
    const int tid = threadIdx.x;

    // ---- pointers ----
    float*  WhhtT  = (float*)(smem);              // [k*256 + r], 64KB (phase 1)
    float*  WtfT   = (float*)(smem + OFF_WTF);    // [k*64 + j]
    float*  WmixTT = (float*)(smem + OFF_WMT);    // [k*64 + j]
    float*  WmixOT = (float*)(smem + OFF_WMO);    // [q*64 + j]
    float*  tscr   = (float*)(smem + OFF_TSCR);
    float*  h_t    = tscr;          // 64
    float*  c_t    = tscr + 64;     // 64
    float*  gates  = tscr + 128;    // 256
    float*  tsv    = tscr + 384;    // 64
    float*  bofm   = tscr + 448;    // 64
    float*  part   = tscr + 512;    // 128
    float*  btg    = tscr + 640;    // 256

    float4* whh4 = (float4*)(smem);
    float4* wc4  = (float4*)(smem + OFF_WC);
    float4* wih4 = (float4*)(smem + OFF_WIH);
    float4* bg4  = (float4*)(smem + OFF_BG);
    float2* w1p  = (float2*)(smem + OFF_W1);
    float2* w2p  = (float2*)(smem + OFF_W2);
    float2* b1p  = (float2*)(smem + OFF_B1);
    float2* b2p  = (float2*)(smem + OFF_B2);
    unsigned long long* hsh2 = (unsigned long long*)(smem + OFF_H2);
    unsigned long long* msh2 = (unsigned long long*)(smem + OFF_M2);

    // =========================================================
    // Phase 1: stage t-branch scratch (all transposed for LDS)
    // =========================================================
    for (int i = tid; i < 16384; i += CTA_THREADS) {
        int r = i >> 6, k = i & 63;
        WhhtT[k * 256 + r] = Whh_t[i];
    }
    for (int i = tid; i < 4096; i += CTA_THREADS) {
        int j = i >> 6, k = i & 63;
        WtfT[k * 64 + j]   = Wtf[i];
        WmixTT[k * 64 + j] = Wmix[j * 128 + k];
        WmixOT[k * 64 + j] = Wmix[j * 128 + 64 + k];
    }
    for (int i = tid; i < 256; i += CTA_THREADS) btg[i] = bih_t[i] + bhh_t[i];
    if (tid < 64) { h_t[tid] = 0.f; c_t[tid] = 0.f; }
    float btf_r = (tid < 64) ? btf[tid] : 0.f;
    float bmix_r = (tid < 64) ? bmix[tid] : 0.f;
    __syncthreads();

    // bofmix[j] = sum_q WmixO[j][q] * bof[q]
    {
        int j = tid & 63, hf = tid >> 6;
        float p = 0.f;
#pragma unroll 8
        for (int q = 0; q < 32; q++) p = fmaf(WmixOT[(hf * 32 + q) * 64 + j], bof[hf * 32 + q], p);
        part[tid] = p;
    }
    __syncthreads();
    if (tid < 64) bofm[tid] = part[tid] + part[64 + tid];
    __syncthreads();
    float bmixsum_r = (tid < 64) ? (bmix_r + bofm[tid]) : 0.f;

    // ---- per-CTA t-LSTM scan (batch-independent) -> tc4 ----
    {
        const int r0 = tid, r1 = tid + 128;
        const float bt0 = btg[r0], bt1 = btg[r1];
        const int j = tid & 63, hf = tid >> 6;
        float* tcf = (float*)(smem + OFF_TC);
        for (int s = 0; s < TSTEPS; s++) {
            float a0 = bt0, a1 = bt1;
#pragma unroll 8
            for (int k = 0; k < 64; k++) {
                float hk = h_t[k];
                a0 = fmaf(WhhtT[k * 256 + r0], hk, a0);
                a1 = fmaf(WhhtT[k * 256 + r1], hk, a1);
            }
            gates[r0] = a0; gates[r1] = a1;
            __syncthreads();
            if (tid < 64) {
                float i_ = sigf(gates[tid]), f_ = sigf(gates[64 + tid]);
                float g_ = tanha(gates[128 + tid]), o_ = sigf(gates[192 + tid]);
                float cn = f_ * c_t[tid] + i_ * g_;
                c_t[tid] = cn;
                h_t[tid] = o_ * tanha(cn);
            }
            __syncthreads();
            {
                float p = 0.f;
#pragma unroll 8
                for (int k = 0; k < 32; k++) p = fmaf(WtfT[(hf * 32 + k) * 64 + j], h_t[hf * 32 + k], p);
                part[tid] = p;
            }
            __syncthreads();
            if (tid < 64) tsv[tid] = btf_r + part[tid] + part[64 + tid];
            __syncthreads();
            {
                float p = 0.f;
#pragma unroll 8
                for (int k = 0; k < 32; k++) p = fmaf(WmixTT[(hf * 32 + k) * 64 + j], tsv[hf * 32 + k], p);
                part[tid] = p;
            }
            __syncthreads();
            if (tid < 64) {
                float v = bmixsum_r + part[tid] + part[64 + tid];
                // tc4[s*16 + (j&15)] component (j>>4)
                tcf[(s * 16 + (tid & 15)) * 4 + (tid >> 4)] = v;
            }
        }
    }
    __syncthreads();

    // =========================================================
    // Phase 2: fold wc4 = WmixO @ Wof ; stage main-loop weights
    // =========================================================
    for (int idx = tid; idx < 1024; idx += CTA_THREADS) {
        int k = idx >> 4, sb = idx & 15;
        float s0 = 0.f, s1 = 0.f, s2 = 0.f, s3 = 0.f;
#pragma unroll 8
        for (int q = 0; q < 64; q++) {
            float wv = Wof[q * 64 + k];
            s0 = fmaf(WmixOT[q * 64 + sb],      wv, s0);
            s1 = fmaf(WmixOT[q * 64 + sb + 16], wv, s1);
            s2 = fmaf(WmixOT[q * 64 + sb + 32], wv, s2);
            s3 = fmaf(WmixOT[q * 64 + sb + 48], wv, s3);
        }
        wc4[idx] = make_float4(s0, s1, s2, s3);
    }
    for (int idx = tid; idx < 4096; idx += CTA_THREADS) {
        int k = idx >> 6, j = idx & 63;
        whh4[idx] = make_float4(Whh_o[j * 64 + k], Whh_o[(64 + j) * 64 + k],
                                Whh_o[(128 + j) * 64 + k], Whh_o[(192 + j) * 64 + k]);
    }
    for (int idx = tid; idx < 1024; idx += CTA_THREADS) {
        int k = idx >> 4, sb = idx & 15;
        w1p[idx] = make_float2(W1[sb * 64 + k], W1[(sb + 16) * 64 + k]);
    }
    for (int idx = tid; idx < 512; idx += CTA_THREADS) {
        int k = idx >> 4, sb = idx & 15;
        w2p[idx] = make_float2(W2[sb * 32 + k], W2[(sb + 16) * 32 + k]);
    }
    if (tid < 128) {
        int xi = tid >> 6, j = tid & 63;
        wih4[tid] = make_float4(Wih_o[j * 2 + xi], Wih_o[(64 + j) * 2 + xi],
                                Wih_o[(128 + j) * 2 + xi], Wih_o[(192 + j) * 2 + xi]);
    }
    if (tid < 64) {
        bg4[tid] = make_float4(bih_o[tid] + bhh_o[tid], bih_o[64 + tid] + bhh_o[64 + tid],
                               bih_o[128 + tid] + bhh_o[128 + tid], bih_o[192 + tid] + bhh_o[192 + tid]);
    }
    if (tid < 16) {
        b1p[tid] = make_float2(b1[tid], b1[tid + 16]);
        b2p[tid] = make_float2(b2[tid], b2[tid + 16]);
    }

    // ---- per-thread mapping ----
    const int lane = tid & 31;
    const int sub  = lane & 15;
    const int rl   = (tid >> 5) * 2 + (lane >> 4);
    const int row  = blockIdx.x * ROWS_PER_CTA + rl;
    unsigned long long* hrow2 = hsh2 + rl * 64;
    unsigned long long* mrow2 = msh2 + rl * 64;

    hrow2[sub] = 0ull; hrow2[sub + 16] = 0ull; hrow2[sub + 32] = 0ull; hrow2[sub + 48] = 0ull;
    float c0 = 0.f, c1 = 0.f, c2 = 0.f, c3 = 0.f;

    // zero c_out
    {
        int cb = BSZ * TSTEPS * 2 + row * TSTEPS;
#pragma unroll
        for (int q = 0; q < 4; q++) {
            int o = cb + sub + 16 * q;
            if (o < out_size) out[o] = 0.f;
        }
    }

    const float w30a = W3[sub], w30b = W3[sub + 16];
    const float w31a = W3[32 + sub], w31b = W3[32 + sub + 16];
    const float b30 = b3[0], b31 = b3[1];

    __syncthreads();

    // =========================================================
    // Phase 3: main loop (packed f32x2 math)
    // =========================================================
    const ulonglong2* bgp  = (const ulonglong2*)bg4;
    const ulonglong2* wihp = (const ulonglong2*)wih4;
    const ulonglong2* whp  = (const ulonglong2*)whh4;
    const ulonglong2* wcp  = (const ulonglong2*)wc4;
    const ulonglong2* tcp  = (const ulonglong2*)(smem + OFF_TC);
    const unsigned long long* w1u = (const unsigned long long*)w1p;
    const unsigned long long* b1u = (const unsigned long long*)b1p;

    float b0x, b0y, bu1x, bu1y, bu2x, bu2y;

    auto cell = [&](float x0, float x1) {
        ulonglong2 A0 = bgp[sub], A1 = bgp[sub + 16], A2 = bgp[sub + 32], A3 = bgp[sub + 48];
        unsigned long long x0d = pk2(x0), x1d = pk2(x1);
        {
            ulonglong2 w;
            w = wihp[sub];           fma2(A0.x, w.x, x0d); fma2(A0.y, w.y, x0d);
            w = wihp[64 + sub];      fma2(A0.x, w.x, x1d); fma2(A0.y, w.y, x1d);
            w = wihp[sub + 16];      fma2(A1.x, w.x, x0d); fma2(A1.y, w.y, x0d);
            w = wihp[64 + sub + 16]; fma2(A1.x, w.x, x1d); fma2(A1.y, w.y, x1d);
            w = wihp[sub + 32];      fma2(A2.x, w.x, x0d); fma2(A2.y, w.y, x0d);
            w = wihp[64 + sub + 32]; fma2(A2.x, w.x, x1d); fma2(A2.y, w.y, x1d);
            w = wihp[sub + 48];      fma2(A3.x, w.x, x0d); fma2(A3.y, w.y, x0d);
            w = wihp[64 + sub + 48]; fma2(A3.x, w.x, x1d); fma2(A3.y, w.y, x1d);
        }
#pragma unroll 4
        for (int k = 0; k < 64; k++) {
            unsigned long long hd = hrow2[k];
            const ulonglong2* wk = whp + k * 64;
            ulonglong2 w;
            w = wk[sub];      fma2(A0.x, w.x, hd); fma2(A0.y, w.y, hd);
            w = wk[sub + 16]; fma2(A1.x, w.x, hd); fma2(A1.y, w.y, hd);
            w = wk[sub + 32]; fma2(A2.x, w.x, hd); fma2(A2.y, w.y, hd);
            w = wk[sub + 48]; fma2(A3.x, w.x, hd); fma2(A3.y, w.y, hd);
        }
        float2 vif, vgo;
        float i_, f_, g_, o_;
        vif = upk(A0.x); vgo = upk(A0.y);
        i_ = sigf(vif.x); f_ = sigf(vif.y); g_ = tanha(vgo.x); o_ = sigf(vgo.y);
        c0 = f_ * c0 + i_ * g_; float h0 = o_ * tanha(c0);
        vif = upk(A1.x); vgo = upk(A1.y);
        i_ = sigf(vif.x); f_ = sigf(vif.y); g_ = tanha(vgo.x); o_ = sigf(vgo.y);
        c1 = f_ * c1 + i_ * g_; float h1 = o_ * tanha(c1);
        vif = upk(A2.x); vgo = upk(A2.y);
        i_ = sigf(vif.x); f_ = sigf(vif.y); g_ = tanha(vgo.x); o_ = sigf(vgo.y);
        c2 = f_ * c2 + i_ * g_; float h2v = o_ * tanha(c2);
        vif = upk(A3.x); vgo = upk(A3.y);
        i_ = sigf(vif.x); f_ = sigf(vif.y); g_ = tanha(vgo.x); o_ = sigf(vgo.y);
        c3 = f_ * c3 + i_ * g_; float h3 = o_ * tanha(c3);
        __syncwarp();
        hrow2[sub] = pk2(h0); hrow2[sub + 16] = pk2(h1);
        hrow2[sub + 32] = pk2(h2v); hrow2[sub + 48] = pk2(h3);
        __syncwarp();
    };

    auto mix = [&](int s) {
        ulonglong2 M = tcp[s * 16 + sub];
#pragma unroll 4
        for (int k = 0; k < 64; k++) {
            unsigned long long hd = hrow2[k];
            ulonglong2 w = wcp[k * 16 + sub];
            fma2(M.x, w.x, hd); fma2(M.y, w.y, hd);
        }
        float2 m01 = upk(M.x), m23 = upk(M.y);
        __syncwarp();
        mrow2[sub] = pk2(m01.x); mrow2[sub + 16] = pk2(m01.y);
        mrow2[sub + 32] = pk2(m23.x); mrow2[sub + 48] = pk2(m23.y);
        __syncwarp();
        unsigned long long ss = b1u[sub];
#pragma unroll 4
        for (int k = 0; k < 64; k++) {
            fma2(ss, w1u[k * 16 + sub], mrow2[k]);
        }
        float2 sf = upk(ss);
        float s1 = lrelu(sf.x), s2 = lrelu(sf.y);
        float2 cb2 = b2p[sub];
        float t1 = cb2.x, t2 = cb2.y;
        const int base16 = lane & 16;
#pragma unroll
        for (int k = 0; k < 16; k++) {
            float ak = __shfl_sync(0xffffffffu, s1, base16 + k, 32);
            float2 w = w2p[k * 16 + sub];
            t1 = fmaf(w.x, ak, t1); t2 = fmaf(w.y, ak, t2);
        }
#pragma unroll
        for (int k = 0; k < 16; k++) {
            float ak = __shfl_sync(0xffffffffu, s2, base16 + k, 32);
            float2 w = w2p[(k + 16) * 16 + sub];
            t1 = fmaf(w.x, ak, t1); t2 = fmaf(w.y, ak, t2);
        }
        t1 = lrelu(t1); t2 = lrelu(t2);
        float p0 = t1 * w30a + t2 * w30b;
        float p1 = t1 * w31a + t2 * w31b;
#pragma unroll
        for (int off = 8; off > 0; off >>= 1) {
            p0 += __shfl_xor_sync(0xffffffffu, p0, off, 32);
            p1 += __shfl_xor_sync(0xffffffffu, p1, off, 32);
        }
        float yx = p0 + b30 + bu2x + (bu2x - b0x) * 0.5f;
        float yy = p1 + b31 + bu2y + (bu2y - b0y) * 0.5f;
        if (sub == 0) {
            out[row * (TSTEPS * 2) + s * 2]     = yx;
            out[row * (TSTEPS * 2) + s * 2 + 1] = yy;
        }
        b0x = bu1x; b0y = bu1y; bu1x = bu2x; bu1y = bu2y; bu2x = yx; bu2y = yy;
    };

    // ---- observation scan (8 steps) ----
    const float* orow = obsv + row * 16;
#pragma unroll 1
    for (int t = 0; t < 8; t++) cell(orow[t * 2], orow[t * 2 + 1]);

    b0x = orow[10]; b0y = orow[11];
    bu1x = orow[12]; bu1y = orow[13];
    bu2x = orow[14]; bu2y = orow[15];

    // ---- autoregressive rollout ----
    mix(0);
#pragma unroll 1
    for (int s = 1; s < TSTEPS; s++) {
        cell(bu2x, bu2y);
        mix(s);
    }
}

extern "C" void kernel_launch(void* const* d_in, const int* in_sizes, int n_in,
                              void* d_out, int out_size)
{
    const float* obsv  = (const float*)d_in[0];
    // d_in[1] = teom: unused (reference feeds zeros into the t-LSTM)
    const float* Wih_o = (const float*)d_in[2];
    const float* Whh_o = (const float*)d_in[3];
    const float* bih_o = (const float*)d_in[4];
    const float* bhh_o = (const float*)d_in[5];
    // d_in[6] = Wih_t: unused (x == 0)
    const float* Whh_t = (const float*)d_in[7];
    const float* bih_t = (const float*)d_in[8];
    const float* bhh_t = (const float*)d_in[9];
    const float* Wof   = (const float*)d_in[10];
    const float* bof   = (const float*)d_in[11];
    const float* Wtf   = (const float*)d_in[12];
    const float* btf   = (const float*)d_in[13];
    const float* Wmix  = (const float*)d_in[14];
    const float* bmix  = (const float*)d_in[15];
    const float* W1    = (const float*)d_in[16];
    const float* b1    = (const float*)d_in[17];
    const float* W2    = (const float*)d_in[18];
    const float* b2    = (const float*)d_in[19];
    const float* W3    = (const float*)d_in[20];
    const float* b3    = (const float*)d_in[21];

    cudaFuncSetAttribute(navnet_fused_kernel, cudaFuncAttributeMaxDynamicSharedMemorySize, SMEM_BYTES);
    navnet_fused_kernel<<<GRID_CTAS, CTA_THREADS, SMEM_BYTES>>>(
        obsv, Wih_o, Whh_o, bih_o, bhh_o,
        Whh_t, bih_t, bhh_t, Wof, bof, Wtf, btf, Wmix, bmix,
        W1, b1, W2, b2, W3, b3,
        (float*)d_out, out_size);
}

// round 4
// speedup vs baseline: 2.5987x; 1.3246x over previous
#include <cuda_runtime.h>

#define HID 64
#define BSZ 1024
#define TSTEPS 64
#define ROWS_PER_CTA 8
#define CTA_THREADS 256
#define GRID_CTAS 128

// ---- shared memory layout (bytes) ----
#define OFF_WCA   65536    // float2[1024]  8KB  wcA: {Wc[sub][k],Wc[sub+16][k]}
#define OFF_WCB   73728    // float2[1024]  8KB
#define OFF_TCA   81920    // float2[1024]  8KB  per-step t-const, j in {sub,sub+16}
#define OFF_TCB   90112    // float2[1024]  8KB
#define OFF_WIH   98304    // float4[128]   2KB
#define OFF_BG    100352   // float4[64]    1KB
#define OFF_W1    101376   // float2[1024]  8KB
#define OFF_W2    109568   // float2[512]   4KB
#define OFF_B1    113664   // float2[16]
#define OFF_B2    113792   // float2[16]
#define OFF_H     113920   // float[8][64]  2KB
#define OFF_M     115968   // float[8][64]  2KB
#define OFF_PS4   118016   // float4[4][128] 8KB  gate partials [g][rl*16+sub]
#define OFF_PS2   126208   // float2[128]   1KB   W1 partials
#define OFF_YSH   127232   // float[16]
#define OFF_WTF   127296   // float[4096] 16KB (t-phase scratch)
#define OFF_WMT   143680   // float[4096] 16KB
#define OFF_WMO   160064   // float[4096] 16KB
#define OFF_TSCR  176448   // float[1024] 4KB
#define SMEM_BYTES 180608

__device__ __forceinline__ float sigf(float x) { return 1.0f / (1.0f + __expf(-x)); }
__device__ __forceinline__ float tanha(float x) { return 2.0f / (1.0f + __expf(-2.0f * x)) - 1.0f; }
__device__ __forceinline__ float lrelu(float v) { return v >= 0.0f ? v : 0.1f * v; }
__device__ __forceinline__ float4 f4fma(float4 w, float h, float4 a) {
    a.x = fmaf(w.x, h, a.x); a.y = fmaf(w.y, h, a.y);
    a.z = fmaf(w.z, h, a.z); a.w = fmaf(w.w, h, a.w);
    return a;
}

__global__ void __launch_bounds__(CTA_THREADS) navnet_fused_kernel(
    const float* __restrict__ obsv,
    const float* __restrict__ Wih_o, const float* __restrict__ Whh_o,
    const float* __restrict__ bih_o, const float* __restrict__ bhh_o,
    const float* __restrict__ Whh_t, const float* __restrict__ bih_t,
    const float* __restrict__ bhh_t, const float* __restrict__ Wof,
    const float* __restrict__ bof, const float* __restrict__ Wtf,
    const float* __restrict__ btf, const float* __restrict__ Wmix,
    const float* __restrict__ bmix,
    const float* __restrict__ W1, const float* __restrict__ b1,
    const float* __restrict__ W2, const float* __restrict__ b2,
    const float* __restrict__ W3, const float* __restrict__ b3,
    float* __restrict__ out, int out_size)
{
    extern __shared__ char smem[];
    const int tid = threadIdx.x;

    // ---- pointers ----
    float*  WhhtT  = (float*)(smem);              // t-phase overlay of whh4
    float*  WtfT   = (float*)(smem + OFF_WTF);
    float*  WmixTT = (float*)(smem + OFF_WMT);
    float*  WmixOT = (float*)(smem + OFF_WMO);
    float*  tscr   = (float*)(smem + OFF_TSCR);
    float*  h_t    = tscr;          // 64
    float*  c_t    = tscr + 64;     // 64
    float*  gates  = tscr + 128;    // 256
    float*  tsv    = tscr + 384;    // 64
    float*  part   = tscr + 512;    // 256
    float*  btg    = tscr + 768;    // 256

    float4* whh4 = (float4*)(smem);
    float2* wcA  = (float2*)(smem + OFF_WCA);
    float2* wcB  = (float2*)(smem + OFF_WCB);
    float2* tcA  = (float2*)(smem + OFF_TCA);
    float2* tcB  = (float2*)(smem + OFF_TCB);
    float4* wih4 = (float4*)(smem + OFF_WIH);
    float4* bg4  = (float4*)(smem + OFF_BG);
    float2* w1p  = (float2*)(smem + OFF_W1);
    float2* w2p  = (float2*)(smem + OFF_W2);
    float2* b1p  = (float2*)(smem + OFF_B1);
    float2* b2p  = (float2*)(smem + OFF_B2);
    float*  hsh  = (float*)(smem + OFF_H);
    float*  msh  = (float*)(smem + OFF_M);
    float4* psh4 = (float4*)(smem + OFF_PS4);
    float2* psh2 = (float2*)(smem + OFF_PS2);
    float*  ysh  = (float*)(smem + OFF_YSH);

    // =========================================================
    // Phase 1: stage t-branch scratch (transposed for LDS)
    // =========================================================
    for (int i = tid; i < 16384; i += CTA_THREADS) {
        int r = i >> 6, k = i & 63;
        WhhtT[k * 256 + r] = Whh_t[i];
    }
    for (int i = tid; i < 4096; i += CTA_THREADS) {
        int j = i >> 6, k = i & 63;
        WtfT[k * 64 + j]   = Wtf[i];
        WmixTT[k * 64 + j] = Wmix[j * 128 + k];
        WmixOT[k * 64 + j] = Wmix[j * 128 + 64 + k];
    }
    btg[tid] = bih_t[tid] + bhh_t[tid];
    if (tid < 64) { h_t[tid] = 0.f; c_t[tid] = 0.f; }
    float btf_r  = (tid < 64) ? btf[tid]  : 0.f;
    float bmix_r = (tid < 64) ? bmix[tid] : 0.f;
    __syncthreads();

    // bofmix[j] = sum_q WmixO[j][q] * bof[q]  (4-way k split)
    {
        int j = tid & 63, qt = tid >> 6;
        float p = 0.f;
#pragma unroll
        for (int q = 0; q < 16; q++)
            p = fmaf(WmixOT[(qt * 16 + q) * 64 + j], bof[qt * 16 + q], p);
        part[tid] = p;
    }
    __syncthreads();
    float bmixsum_r = 0.f;
    if (tid < 64)
        bmixsum_r = bmix_r + part[tid] + part[64 + tid] + part[128 + tid] + part[192 + tid];
    __syncthreads();

    // ---- t-LSTM scan (batch-independent) -> tcA/tcB ----
    {
        const float bt = btg[tid];
        const int j = tid & 63, qt = tid >> 6;
        for (int s = 0; s < TSTEPS; s++) {
            float a = bt;
#pragma unroll 8
            for (int k = 0; k < 64; k++) a = fmaf(WhhtT[k * 256 + tid], h_t[k], a);
            gates[tid] = a;
            __syncthreads();
            if (tid < 64) {
                float i_ = sigf(gates[tid]), f_ = sigf(gates[64 + tid]);
                float g_ = tanha(gates[128 + tid]), o_ = sigf(gates[192 + tid]);
                float cn = f_ * c_t[tid] + i_ * g_;
                c_t[tid] = cn;
                h_t[tid] = o_ * tanha(cn);
            }
            __syncthreads();
            {
                float p = 0.f;
#pragma unroll
                for (int k = 0; k < 16; k++)
                    p = fmaf(WtfT[(qt * 16 + k) * 64 + j], h_t[qt * 16 + k], p);
                part[tid] = p;
            }
            __syncthreads();
            if (tid < 64) tsv[tid] = btf_r + part[tid] + part[64 + tid] + part[128 + tid] + part[192 + tid];
            __syncthreads();
            {
                float p = 0.f;
#pragma unroll
                for (int k = 0; k < 16; k++)
                    p = fmaf(WmixTT[(qt * 16 + k) * 64 + j], tsv[qt * 16 + k], p);
                part[tid] = p;
            }
            __syncthreads();
            if (tid < 64) {
                float v = bmixsum_r + part[tid] + part[64 + tid] + part[128 + tid] + part[192 + tid];
                float* dst = (tid < 32) ? (float*)tcA : (float*)tcB;
                dst[(s * 16 + (tid & 15)) * 2 + ((tid >> 4) & 1)] = v;
            }
        }
    }
    __syncthreads();

    // =========================================================
    // Phase 2: fold wc = WmixO @ Wof ; stage main-loop weights
    // =========================================================
    for (int idx = tid; idx < 1024; idx += CTA_THREADS) {
        int k = idx >> 4, sb = idx & 15;
        float s0 = 0.f, s1 = 0.f, s2 = 0.f, s3 = 0.f;
#pragma unroll 8
        for (int q = 0; q < 64; q++) {
            float wv = Wof[q * 64 + k];
            s0 = fmaf(WmixOT[q * 64 + sb],      wv, s0);
            s1 = fmaf(WmixOT[q * 64 + sb + 16], wv, s1);
            s2 = fmaf(WmixOT[q * 64 + sb + 32], wv, s2);
            s3 = fmaf(WmixOT[q * 64 + sb + 48], wv, s3);
        }
        wcA[idx] = make_float2(s0, s1);
        wcB[idx] = make_float2(s2, s3);
    }
    __syncthreads();  // wc fold reads WmixOT; whh4 staging below overwrites WhhtT only
    for (int idx = tid; idx < 4096; idx += CTA_THREADS) {
        int k = idx >> 6, j = idx & 63;
        whh4[idx] = make_float4(Whh_o[j * 64 + k], Whh_o[(64 + j) * 64 + k],
                                Whh_o[(128 + j) * 64 + k], Whh_o[(192 + j) * 64 + k]);
    }
    for (int idx = tid; idx < 1024; idx += CTA_THREADS) {
        int k = idx >> 4, sb = idx & 15;
        w1p[idx] = make_float2(W1[sb * 64 + k], W1[(sb + 16) * 64 + k]);
    }
    for (int idx = tid; idx < 512; idx += CTA_THREADS) {
        int k = idx >> 4, sb = idx & 15;
        w2p[idx] = make_float2(W2[sb * 32 + k], W2[(sb + 16) * 32 + k]);
    }
    if (tid < 128) {
        int xi = tid >> 6, j = tid & 63;
        wih4[tid] = make_float4(Wih_o[j * 2 + xi], Wih_o[(64 + j) * 2 + xi],
                                Wih_o[(128 + j) * 2 + xi], Wih_o[(192 + j) * 2 + xi]);
    }
    if (tid < 64) {
        bg4[tid] = make_float4(bih_o[tid] + bhh_o[tid], bih_o[64 + tid] + bhh_o[64 + tid],
                               bih_o[128 + tid] + bhh_o[128 + tid], bih_o[192 + tid] + bhh_o[192 + tid]);
    }
    if (tid < 16) {
        b1p[tid] = make_float2(b1[tid], b1[tid + 16]);
        b2p[tid] = make_float2(b2[tid], b2[tid + 16]);
    }

    // ---- per-thread mapping: 2 warps (k-halves) per 2-row pair ----
    const int lane  = tid & 31;
    const int sub   = lane & 15;
    const int warp  = tid >> 5;
    const int khalf = warp & 1;          // 0 = warp A, 1 = warp B
    const int pair  = warp >> 1;         // 0..3
    const int rl    = pair * 2 + (lane >> 4);
    const int row   = blockIdx.x * ROWS_PER_CTA + rl;
    float* hrow = hsh + rl * 64;
    float* mrow = msh + rl * 64;
    const float4* hrow4 = (const float4*)hrow;

    if (khalf == 0) {
        hrow[sub] = 0.f; hrow[sub + 16] = 0.f; hrow[sub + 32] = 0.f; hrow[sub + 48] = 0.f;
    }
    float c0 = 0.f, c1 = 0.f, c2 = 0.f, c3 = 0.f;  // live in warp A only

    // zero c_out region
    for (int i = tid; i < ROWS_PER_CTA * TSTEPS; i += CTA_THREADS) {
        int o = BSZ * TSTEPS * 2 + blockIdx.x * ROWS_PER_CTA * TSTEPS + i;
        if (o < out_size) out[o] = 0.f;
    }

    const float w30a = W3[sub], w30b = W3[sub + 16];
    const float w31a = W3[32 + sub], w31b = W3[32 + sub + 16];
    const float b30 = b3[0], b31 = b3[1];

    __syncthreads();

    // =========================================================
    // Phase 3: main loop
    // =========================================================
    float b0x, b0y, bu1x, bu1y, bu2x, bu2y;

    auto cell = [&](float x0, float x1) {
        float4 A0, A1, A2, A3;
        if (khalf == 0) {
            A0 = bg4[sub]; A1 = bg4[sub + 16]; A2 = bg4[sub + 32]; A3 = bg4[sub + 48];
            A0 = f4fma(wih4[sub], x0, A0);       A0 = f4fma(wih4[64 + sub], x1, A0);
            A1 = f4fma(wih4[sub + 16], x0, A1);  A1 = f4fma(wih4[64 + sub + 16], x1, A1);
            A2 = f4fma(wih4[sub + 32], x0, A2);  A2 = f4fma(wih4[64 + sub + 32], x1, A2);
            A3 = f4fma(wih4[sub + 48], x0, A3);  A3 = f4fma(wih4[64 + sub + 48], x1, A3);
        } else {
            A0 = make_float4(0.f, 0.f, 0.f, 0.f); A1 = A0; A2 = A0; A3 = A0;
        }
#pragma unroll
        for (int k4 = 0; k4 < 8; k4++) {
            float4 hv = hrow4[khalf * 8 + k4];
            int b = (khalf * 8 + k4) * 256;
#define STEPK(hk, off)                                   \
            A0 = f4fma(whh4[b + (off) + sub], hk, A0);       \
            A1 = f4fma(whh4[b + (off) + sub + 16], hk, A1);  \
            A2 = f4fma(whh4[b + (off) + sub + 32], hk, A2);  \
            A3 = f4fma(whh4[b + (off) + sub + 48], hk, A3);
            STEPK(hv.x, 0) STEPK(hv.y, 64) STEPK(hv.z, 128) STEPK(hv.w, 192)
#undef STEPK
        }
        if (khalf) {
            psh4[rl * 16 + sub]       = A0;
            psh4[128 + rl * 16 + sub] = A1;
            psh4[256 + rl * 16 + sub] = A2;
            psh4[384 + rl * 16 + sub] = A3;
        }
        __syncthreads();  // bar1: partials ready
        if (!khalf) {
            float4 P;
            P = psh4[rl * 16 + sub];       A0.x += P.x; A0.y += P.y; A0.z += P.z; A0.w += P.w;
            P = psh4[128 + rl * 16 + sub]; A1.x += P.x; A1.y += P.y; A1.z += P.z; A1.w += P.w;
            P = psh4[256 + rl * 16 + sub]; A2.x += P.x; A2.y += P.y; A2.z += P.z; A2.w += P.w;
            P = psh4[384 + rl * 16 + sub]; A3.x += P.x; A3.y += P.y; A3.z += P.z; A3.w += P.w;
            float i_, f_, g_, o_;
            i_ = sigf(A0.x); f_ = sigf(A0.y); g_ = tanha(A0.z); o_ = sigf(A0.w);
            c0 = f_ * c0 + i_ * g_; float h0 = o_ * tanha(c0);
            i_ = sigf(A1.x); f_ = sigf(A1.y); g_ = tanha(A1.z); o_ = sigf(A1.w);
            c1 = f_ * c1 + i_ * g_; float h1 = o_ * tanha(c1);
            i_ = sigf(A2.x); f_ = sigf(A2.y); g_ = tanha(A2.z); o_ = sigf(A2.w);
            c2 = f_ * c2 + i_ * g_; float h2 = o_ * tanha(c2);
            i_ = sigf(A3.x); f_ = sigf(A3.y); g_ = tanha(A3.z); o_ = sigf(A3.w);
            c3 = f_ * c3 + i_ * g_; float h3 = o_ * tanha(c3);
            hrow[sub] = h0; hrow[sub + 16] = h1; hrow[sub + 32] = h2; hrow[sub + 48] = h3;
        }
        __syncthreads();  // bar2: h ready
    };

    auto mix = [&](int sidx) {
        const float2* tcX = khalf ? tcB : tcA;
        const float2* wcX = khalf ? wcB : wcA;
        float2 M = tcX[sidx * 16 + sub];
#pragma unroll
        for (int k4 = 0; k4 < 16; k4++) {
            float4 hv = hrow4[k4];
            int b = k4 * 64;
            float2 w;
            w = wcX[b + sub];      M.x = fmaf(w.x, hv.x, M.x); M.y = fmaf(w.y, hv.x, M.y);
            w = wcX[b + 16 + sub]; M.x = fmaf(w.x, hv.y, M.x); M.y = fmaf(w.y, hv.y, M.y);
            w = wcX[b + 32 + sub]; M.x = fmaf(w.x, hv.z, M.x); M.y = fmaf(w.y, hv.z, M.y);
            w = wcX[b + 48 + sub]; M.x = fmaf(w.x, hv.w, M.x); M.y = fmaf(w.y, hv.w, M.y);
        }
        mrow[khalf * 32 + sub]      = M.x;
        mrow[khalf * 32 + sub + 16] = M.y;
        __syncwarp();  // each warp reads only its own half of mrow below
        float s1, s2;
        if (!khalf) { float2 bb = b1p[sub]; s1 = bb.x; s2 = bb.y; }
        else        { s1 = 0.f; s2 = 0.f; }
#pragma unroll 8
        for (int k = 0; k < 32; k++) {
            float mk = mrow[khalf * 32 + k];
            float2 w = w1p[(khalf * 32 + k) * 16 + sub];
            s1 = fmaf(w.x, mk, s1); s2 = fmaf(w.y, mk, s2);
        }
        if (khalf) psh2[rl * 16 + sub] = make_float2(s1, s2);
        __syncthreads();  // bar3: W1 partials ready
        if (!khalf) {
            float2 pp = psh2[rl * 16 + sub];
            s1 = lrelu(s1 + pp.x); s2 = lrelu(s2 + pp.y);
            float2 cb2 = b2p[sub];
            float t1 = cb2.x, t2 = cb2.y;
            const int base16 = lane & 16;
#pragma unroll
            for (int k = 0; k < 16; k++) {
                float ak = __shfl_sync(0xffffffffu, s1, base16 + k, 32);
                float2 w = w2p[k * 16 + sub];
                t1 = fmaf(w.x, ak, t1); t2 = fmaf(w.y, ak, t2);
            }
#pragma unroll
            for (int k = 0; k < 16; k++) {
                float ak = __shfl_sync(0xffffffffu, s2, base16 + k, 32);
                float2 w = w2p[(k + 16) * 16 + sub];
                t1 = fmaf(w.x, ak, t1); t2 = fmaf(w.y, ak, t2);
            }
            t1 = lrelu(t1); t2 = lrelu(t2);
            float p0 = t1 * w30a + t2 * w30b;
            float p1 = t1 * w31a + t2 * w31b;
#pragma unroll
            for (int off = 8; off > 0; off >>= 1) {
                p0 += __shfl_xor_sync(0xffffffffu, p0, off, 32);
                p1 += __shfl_xor_sync(0xffffffffu, p1, off, 32);
            }
            float yx = p0 + b30 + bu2x + (bu2x - b0x) * 0.5f;
            float yy = p1 + b31 + bu2y + (bu2y - b0y) * 0.5f;
            if (sub == 0) {
                out[row * (TSTEPS * 2) + sidx * 2]     = yx;
                out[row * (TSTEPS * 2) + sidx * 2 + 1] = yy;
                ysh[rl * 2]     = yx;
                ysh[rl * 2 + 1] = yy;
            }
        }
        __syncthreads();  // bar4: y broadcast
        float yx = ysh[rl * 2], yy = ysh[rl * 2 + 1];
        b0x = bu1x; b0y = bu1y; bu1x = bu2x; bu1y = bu2y; bu2x = yx; bu2y = yy;
    };

    // ---- observation scan (8 steps) ----
    const float* orow = obsv + row * 16;
#pragma unroll 1
    for (int t = 0; t < 8; t++) cell(orow[t * 2], orow[t * 2 + 1]);

    b0x = orow[10]; b0y = orow[11];
    bu1x = orow[12]; bu1y = orow[13];
    bu2x = orow[14]; bu2y = orow[15];

    // ---- autoregressive rollout ----
    mix(0);
#pragma unroll 1
    for (int s = 1; s < TSTEPS; s++) {
        cell(bu2x, bu2y);
        mix(s);
    }
}

extern "C" void kernel_launch(void* const* d_in, const int* in_sizes, int n_in,
                              void* d_out, int out_size)
{
    const float* obsv  = (const float*)d_in[0];
    // d_in[1] = teom: unused (reference feeds zeros into the t-LSTM)
    const float* Wih_o = (const float*)d_in[2];
    const float* Whh_o = (const float*)d_in[3];
    const float* bih_o = (const float*)d_in[4];
    const float* bhh_o = (const float*)d_in[5];
    // d_in[6] = Wih_t: unused (x == 0)
    const float* Whh_t = (const float*)d_in[7];
    const float* bih_t = (const float*)d_in[8];
    const float* bhh_t = (const float*)d_in[9];
    const float* Wof   = (const float*)d_in[10];
    const float* bof   = (const float*)d_in[11];
    const float* Wtf   = (const float*)d_in[12];
    const float* btf   = (const float*)d_in[13];
    const float* Wmix  = (const float*)d_in[14];
    const float* bmix  = (const float*)d_in[15];
    const float* W1    = (const float*)d_in[16];
    const float* b1    = (const float*)d_in[17];
    const float* W2    = (const float*)d_in[18];
    const float* b2    = (const float*)d_in[19];
    const float* W3    = (const float*)d_in[20];
    const float* b3    = (const float*)d_in[21];

    cudaFuncSetAttribute(navnet_fused_kernel, cudaFuncAttributeMaxDynamicSharedMemorySize, SMEM_BYTES);
    navnet_fused_kernel<<<GRID_CTAS, CTA_THREADS, SMEM_BYTES>>>(
        obsv, Wih_o, Whh_o, bih_o, bhh_o,
        Whh_t, bih_t, bhh_t, Wof, bof, Wtf, btf, Wmix, bmix,
        W1, b1, W2, b2, W3, b3,
        (float*)d_out, out_size);
}

// round 5
// speedup vs baseline: 2.6517x; 1.0204x over previous
#include <cuda_runtime.h>

#define HID 64
#define BSZ 1024
#define TSTEPS 64
#define ROWS_PER_CTA 8
#define CTA_THREADS 512
#define GRID_CTAS 128

// ---- shared memory layout (bytes) ----
#define OFF_WCF   65536    // float[64][64] 16KB  wcf[k*64+j] = Wcomb[j][k]
#define OFF_TCF   81920    // float[64][64] 16KB  tcf[s*64+j]
#define OFF_WIH   98304    // float4[128]   2KB
#define OFF_BG    100352   // float4[64]    1KB
#define OFF_W1    101376   // float2[1024]  8KB
#define OFF_W2    109568   // float2[512]   4KB
#define OFF_B1    113664   // float2[16]
#define OFF_B2    113792   // float2[16]
#define OFF_H     113920   // float[2][8][64] 4KB (double-buffered h)
#define OFF_M     118016   // float[8][64]  2KB
#define OFF_PS2   120064   // float2[4][128] 4KB  W1 partials
#define OFF_WTF   124160   // float[4096] 16KB (t-phase scratch)
#define OFF_WMT   140544   // float[4096] 16KB
#define OFF_WMO   156928   // float[4096] 16KB
#define OFF_TSCR  173312   // float[1024] 4KB
#define SMEM_BYTES 177408

__device__ __forceinline__ float sigf(float x) { return 1.0f / (1.0f + __expf(-x)); }
__device__ __forceinline__ float tanha(float x) { return 2.0f / (1.0f + __expf(-2.0f * x)) - 1.0f; }
__device__ __forceinline__ float lrelu(float v) { return v >= 0.0f ? v : 0.1f * v; }
__device__ __forceinline__ float4 f4fma(float4 w, float h, float4 a) {
    a.x = fmaf(w.x, h, a.x); a.y = fmaf(w.y, h, a.y);
    a.z = fmaf(w.z, h, a.z); a.w = fmaf(w.w, h, a.w);
    return a;
}

__global__ void __launch_bounds__(CTA_THREADS) navnet_fused_kernel(
    const float* __restrict__ obsv,
    const float* __restrict__ Wih_o, const float* __restrict__ Whh_o,
    const float* __restrict__ bih_o, const float* __restrict__ bhh_o,
    const float* __restrict__ Whh_t, const float* __restrict__ bih_t,
    const float* __restrict__ bhh_t, const float* __restrict__ Wof,
    const float* __restrict__ bof, const float* __restrict__ Wtf,
    const float* __restrict__ btf, const float* __restrict__ Wmix,
    const float* __restrict__ bmix,
    const float* __restrict__ W1, const float* __restrict__ b1,
    const float* __restrict__ W2, const float* __restrict__ b2,
    const float* __restrict__ W3, const float* __restrict__ b3,
    float* __restrict__ out, int out_size)
{
    extern __shared__ char smem[];
    const int tid = threadIdx.x;

    // ---- pointers ----
    float*  WhhtT  = (float*)(smem);              // t-phase overlay of whh4
    float*  WtfT   = (float*)(smem + OFF_WTF);
    float*  WmixTT = (float*)(smem + OFF_WMT);
    float*  WmixOT = (float*)(smem + OFF_WMO);
    float*  tscr   = (float*)(smem + OFF_TSCR);
    float*  h_t    = tscr;          // 64
    float*  c_t    = tscr + 64;     // 64
    float*  gates  = tscr + 128;    // 256
    float*  tsv    = tscr + 384;    // 64
    float*  part   = tscr + 512;    // 256
    float*  btg    = tscr + 768;    // 256

    float4* whh4 = (float4*)(smem);
    float*  wcf  = (float*)(smem + OFF_WCF);
    float*  tcf  = (float*)(smem + OFF_TCF);
    float4* wih4 = (float4*)(smem + OFF_WIH);
    float4* bg4  = (float4*)(smem + OFF_BG);
    float2* w1p  = (float2*)(smem + OFF_W1);
    float2* w2p  = (float2*)(smem + OFF_W2);
    float2* b1p  = (float2*)(smem + OFF_B1);
    float2* b2p  = (float2*)(smem + OFF_B2);
    float*  hsh  = (float*)(smem + OFF_H);     // 2 buffers of [8][64]
    float*  msh  = (float*)(smem + OFF_M);
    float2* psh2 = (float2*)(smem + OFF_PS2);

    // =========================================================
    // Phase 1: stage t-branch scratch (transposed for LDS)
    // =========================================================
    for (int i = tid; i < 16384; i += CTA_THREADS) {
        int r = i >> 6, k = i & 63;
        WhhtT[k * 256 + r] = Whh_t[i];
    }
    for (int i = tid; i < 4096; i += CTA_THREADS) {
        int j = i >> 6, k = i & 63;
        WtfT[k * 64 + j]   = Wtf[i];
        WmixTT[k * 64 + j] = Wmix[j * 128 + k];
        WmixOT[k * 64 + j] = Wmix[j * 128 + 64 + k];
    }
    if (tid < 256) btg[tid] = bih_t[tid] + bhh_t[tid];
    if (tid < 64) { h_t[tid] = 0.f; c_t[tid] = 0.f; }
    float btf_r  = (tid < 64) ? btf[tid]  : 0.f;
    float bmix_r = (tid < 64) ? bmix[tid] : 0.f;
    __syncthreads();

    // bofmix[j] = sum_q WmixO[j][q] * bof[q]  (4-way k split over first 256 threads)
    if (tid < 256) {
        int j = tid & 63, qt = tid >> 6;
        float p = 0.f;
#pragma unroll
        for (int q = 0; q < 16; q++)
            p = fmaf(WmixOT[(qt * 16 + q) * 64 + j], bof[qt * 16 + q], p);
        part[tid] = p;
    }
    __syncthreads();
    float bmixsum_r = 0.f;
    if (tid < 64)
        bmixsum_r = bmix_r + part[tid] + part[64 + tid] + part[128 + tid] + part[192 + tid];
    __syncthreads();

    // ---- t-LSTM scan (batch-independent) -> tcf[s][j] ----
    {
        const float bt = (tid < 256) ? btg[tid] : 0.f;
        const int j = tid & 63, qt = (tid >> 6) & 3;
        for (int s = 0; s < TSTEPS; s++) {
            if (tid < 256) {
                float a = bt;
#pragma unroll 8
                for (int k = 0; k < 64; k++) a = fmaf(WhhtT[k * 256 + tid], h_t[k], a);
                gates[tid] = a;
            }
            __syncthreads();
            if (tid < 64) {
                float i_ = sigf(gates[tid]), f_ = sigf(gates[64 + tid]);
                float g_ = tanha(gates[128 + tid]), o_ = sigf(gates[192 + tid]);
                float cn = f_ * c_t[tid] + i_ * g_;
                c_t[tid] = cn;
                h_t[tid] = o_ * tanha(cn);
            }
            __syncthreads();
            if (tid < 256) {
                float p = 0.f;
#pragma unroll
                for (int k = 0; k < 16; k++)
                    p = fmaf(WtfT[(qt * 16 + k) * 64 + j], h_t[qt * 16 + k], p);
                part[tid] = p;
            }
            __syncthreads();
            if (tid < 64) tsv[tid] = btf_r + part[tid] + part[64 + tid] + part[128 + tid] + part[192 + tid];
            __syncthreads();
            if (tid < 256) {
                float p = 0.f;
#pragma unroll
                for (int k = 0; k < 16; k++)
                    p = fmaf(WmixTT[(qt * 16 + k) * 64 + j], tsv[qt * 16 + k], p);
                part[tid] = p;
            }
            __syncthreads();
            if (tid < 64)
                tcf[s * 64 + tid] = bmixsum_r + part[tid] + part[64 + tid] + part[128 + tid] + part[192 + tid];
            __syncthreads();
        }
    }

    // =========================================================
    // Phase 2: fold wcf[k][j] = Wcomb[j][k] ; stage main weights
    // =========================================================
    for (int idx = tid; idx < 4096; idx += CTA_THREADS) {
        int k = idx >> 6, j = idx & 63;
        float s = 0.f;
#pragma unroll 8
        for (int q = 0; q < 64; q++)
            s = fmaf(WmixOT[q * 64 + j], Wof[q * 64 + k], s);
        wcf[idx] = s;   // wcf[k*64 + j]
    }
    __syncthreads();  // t-phase reads of WhhtT (smem[0..64KB]) done before overwrite
    for (int idx = tid; idx < 4096; idx += CTA_THREADS) {
        int k = idx >> 6, j = idx & 63;
        whh4[idx] = make_float4(Whh_o[j * 64 + k], Whh_o[(64 + j) * 64 + k],
                                Whh_o[(128 + j) * 64 + k], Whh_o[(192 + j) * 64 + k]);
    }
    for (int idx = tid; idx < 1024; idx += CTA_THREADS) {
        int k = idx >> 4, sb = idx & 15;
        w1p[idx] = make_float2(W1[sb * 64 + k], W1[(sb + 16) * 64 + k]);
    }
    for (int idx = tid; idx < 512; idx += CTA_THREADS) {
        int k = idx >> 4, sb = idx & 15;
        w2p[idx] = make_float2(W2[sb * 32 + k], W2[(sb + 16) * 32 + k]);
    }
    if (tid < 128) {
        int xi = tid >> 6, j = tid & 63;
        wih4[tid] = make_float4(Wih_o[j * 2 + xi], Wih_o[(64 + j) * 2 + xi],
                                Wih_o[(128 + j) * 2 + xi], Wih_o[(192 + j) * 2 + xi]);
    }
    if (tid < 64) {
        bg4[tid] = make_float4(bih_o[tid] + bhh_o[tid], bih_o[64 + tid] + bhh_o[64 + tid],
                               bih_o[128 + tid] + bhh_o[128 + tid], bih_o[192 + tid] + bhh_o[192 + tid]);
    }
    if (tid < 16) {
        b1p[tid] = make_float2(b1[tid], b1[tid + 16]);
        b2p[tid] = make_float2(b2[tid], b2[tid + 16]);
    }

    // ---- per-thread mapping: 4 warps (j-quarters) per 2-row pair ----
    const int lane = tid & 31;
    const int sub  = lane & 15;
    const int warp = tid >> 5;        // 0..15
    const int pair = warp >> 2;       // 0..3
    const int jw   = warp & 3;        // j-quarter
    const int rl   = pair * 2 + (lane >> 4);
    const int row  = blockIdx.x * ROWS_PER_CTA + rl;
    const int j    = jw * 16 + sub;   // this thread's output index (0..63)
    float* mrow = msh + rl * 64;

    // init h buffer 0; per-thread cell state
    hsh[rl * 64 + j] = 0.f;
    float cst = 0.f;
    int hp = 0;

    // zero c_out region
    for (int i = tid; i < ROWS_PER_CTA * TSTEPS; i += CTA_THREADS) {
        int o = BSZ * TSTEPS * 2 + blockIdx.x * ROWS_PER_CTA * TSTEPS + i;
        if (o < out_size) out[o] = 0.f;
    }

    const float w30a = W3[sub], w30b = W3[sub + 16];
    const float w31a = W3[32 + sub], w31b = W3[32 + sub + 16];
    const float b30 = b3[0], b31 = b3[1];

    __syncthreads();

    // =========================================================
    // Phase 3: main loop
    // =========================================================
    float b0x, b0y, bu1x, bu1y, bu2x, bu2y;

    auto cell = [&](float x0, float x1) {
        const float4* hr4 = (const float4*)(hsh + hp * 512 + rl * 64);
        float* hw = hsh + (hp ^ 1) * 512 + rl * 64;
        float4 A = bg4[j];
        A = f4fma(wih4[j], x0, A);
        A = f4fma(wih4[64 + j], x1, A);
#pragma unroll
        for (int k4 = 0; k4 < 16; k4++) {
            float4 hv = hr4[k4];
            int b = k4 * 256;
            A = f4fma(whh4[b + j],       hv.x, A);
            A = f4fma(whh4[b + 64 + j],  hv.y, A);
            A = f4fma(whh4[b + 128 + j], hv.z, A);
            A = f4fma(whh4[b + 192 + j], hv.w, A);
        }
        float i_ = sigf(A.x), f_ = sigf(A.y), g_ = tanha(A.z), o_ = sigf(A.w);
        cst = f_ * cst + i_ * g_;
        hw[j] = o_ * tanha(cst);
        hp ^= 1;
        __syncthreads();  // h visible to all warps
    };

    auto mix = [&](int sidx) {
        const float4* hr4 = (const float4*)(hsh + hp * 512 + rl * 64);
        float M = tcf[sidx * 64 + j];
#pragma unroll
        for (int k4 = 0; k4 < 16; k4++) {
            float4 hv = hr4[k4];
            int b = k4 * 256;
            M = fmaf(wcf[b + j],       hv.x, M);
            M = fmaf(wcf[b + 64 + j],  hv.y, M);
            M = fmaf(wcf[b + 128 + j], hv.z, M);
            M = fmaf(wcf[b + 192 + j], hv.w, M);
        }
        mrow[j] = M;
        __syncwarp();  // warp reads only its own quarter of mrow below
        float s1 = 0.f, s2 = 0.f;
#pragma unroll
        for (int kk = 0; kk < 16; kk++) {
            float mk = mrow[jw * 16 + kk];
            float2 w = w1p[(jw * 16 + kk) * 16 + sub];
            s1 = fmaf(w.x, mk, s1); s2 = fmaf(w.y, mk, s2);
        }
        psh2[jw * 128 + rl * 16 + sub] = make_float2(s1, s2);
        __syncthreads();  // W1 partials ready
        // all 4 warps compute the small tail redundantly (cheaper than idling)
        float2 q0 = psh2[rl * 16 + sub];
        float2 q1 = psh2[128 + rl * 16 + sub];
        float2 q2 = psh2[256 + rl * 16 + sub];
        float2 q3 = psh2[384 + rl * 16 + sub];
        float2 bb = b1p[sub];
        float a1 = lrelu(bb.x + q0.x + q1.x + q2.x + q3.x);
        float a2 = lrelu(bb.y + q0.y + q1.y + q2.y + q3.y);
        float2 cb2 = b2p[sub];
        float t1 = cb2.x, t2 = cb2.y;
        const int base16 = lane & 16;
#pragma unroll
        for (int k = 0; k < 16; k++) {
            float ak = __shfl_sync(0xffffffffu, a1, base16 + k, 32);
            float2 w = w2p[k * 16 + sub];
            t1 = fmaf(w.x, ak, t1); t2 = fmaf(w.y, ak, t2);
        }
#pragma unroll
        for (int k = 0; k < 16; k++) {
            float ak = __shfl_sync(0xffffffffu, a2, base16 + k, 32);
            float2 w = w2p[(k + 16) * 16 + sub];
            t1 = fmaf(w.x, ak, t1); t2 = fmaf(w.y, ak, t2);
        }
        t1 = lrelu(t1); t2 = lrelu(t2);
        float p0 = t1 * w30a + t2 * w30b;
        float p1 = t1 * w31a + t2 * w31b;
#pragma unroll
        for (int off = 8; off > 0; off >>= 1) {
            p0 += __shfl_xor_sync(0xffffffffu, p0, off, 32);
            p1 += __shfl_xor_sync(0xffffffffu, p1, off, 32);
        }
        float yx = p0 + b30 + bu2x + (bu2x - b0x) * 0.5f;
        float yy = p1 + b31 + bu2y + (bu2y - b0y) * 0.5f;
        if (jw == 0 && sub == 0) {
            out[row * (TSTEPS * 2) + sidx * 2]     = yx;
            out[row * (TSTEPS * 2) + sidx * 2 + 1] = yy;
        }
        b0x = bu1x; b0y = bu1y; bu1x = bu2x; bu1y = bu2y; bu2x = yx; bu2y = yy;
    };

    // ---- observation scan (8 steps) ----
    const float* orow = obsv + row * 16;
#pragma unroll 1
    for (int t = 0; t < 8; t++) cell(orow[t * 2], orow[t * 2 + 1]);

    b0x = orow[10]; b0y = orow[11];
    bu1x = orow[12]; bu1y = orow[13];
    bu2x = orow[14]; bu2y = orow[15];

    // ---- autoregressive rollout ----
    mix(0);
#pragma unroll 1
    for (int s = 1; s < TSTEPS; s++) {
        cell(bu2x, bu2y);
        mix(s);
    }
}

extern "C" void kernel_launch(void* const* d_in, const int* in_sizes, int n_in,
                              void* d_out, int out_size)
{
    const float* obsv  = (const float*)d_in[0];
    // d_in[1] = teom: unused (reference feeds zeros into the t-LSTM)
    const float* Wih_o = (const float*)d_in[2];
    const float* Whh_o = (const float*)d_in[3];
    const float* bih_o = (const float*)d_in[4];
    const float* bhh_o = (const float*)d_in[5];
    // d_in[6] = Wih_t: unused (x == 0)
    const float* Whh_t = (const float*)d_in[7];
    const float* bih_t = (const float*)d_in[8];
    const float* bhh_t = (const float*)d_in[9];
    const float* Wof   = (const float*)d_in[10];
    const float* bof   = (const float*)d_in[11];
    const float* Wtf   = (const float*)d_in[12];
    const float* btf   = (const float*)d_in[13];
    const float* Wmix  = (const float*)d_in[14];
    const float* bmix  = (const float*)d_in[15];
    const float* W1    = (const float*)d_in[16];
    const float* b1    = (const float*)d_in[17];
    const float* W2    = (const float*)d_in[18];
    const float* b2    = (const float*)d_in[19];
    const float* W3    = (const float*)d_in[20];
    const float* b3    = (const float*)d_in[21];

    cudaFuncSetAttribute(navnet_fused_kernel, cudaFuncAttributeMaxDynamicSharedMemorySize, SMEM_BYTES);
    navnet_fused_kernel<<<GRID_CTAS, CTA_THREADS, SMEM_BYTES>>>(
        obsv, Wih_o, Whh_o, bih_o, bhh_o,
        Whh_t, bih_t, bhh_t, Wof, bof, Wtf, btf, Wmix, bmix,
        W1, b1, W2, b2, W3, b3,
        (float*)d_out, out_size);
}